// round 3
// baseline (speedup 1.0000x reference)
#include <cuda_runtime.h>
#include <cuda_bf16.h>
#include <math.h>

#define SIZE   512
#define N_PHOS 256
#define H      10
#define THRESH 0.05f

// Max output-tile height: ceil span of disk (<=31) + 2H + 1 = 52
#define MAX_OH 52
// Max intermediate width: MAX_OH + 2H = 72 (+1 pad)
#define MAX_TW 73

__device__ int g_max_bits;          // clamped-image max as float bits (>=0 so int cmp works)

static __device__ __forceinline__ int refl(int i) {
    if (i < 0)        i = -i;
    if (i > SIZE - 1) i = 2 * (SIZE - 1) - i;
    return i;
}

// ---------------------------------------------------------------------------
// K0: zero the image accumulator + reset the max scratch
// ---------------------------------------------------------------------------
__global__ void k_zero(float* __restrict__ img) {
    int i = blockIdx.x * blockDim.x + threadIdx.x;
    if (i < SIZE * SIZE) img[i] = 0.0f;
    if (i == 0) g_max_bits = 0;
}

// ---------------------------------------------------------------------------
// K1: one block per phosphene. Analytic disk mask -> vertical blur into smem
//     -> horizontal blur -> threshold -> atomicAdd into image.
// ---------------------------------------------------------------------------
__global__ __launch_bounds__(256) void k_phos(
    const float* __restrict__ phoscoding,
    const float* __restrict__ grid,
    float* __restrict__ img)
{
    const int p   = blockIdx.x;
    const int tid = threadIdx.x;

    const float bright = phoscoding[p];
    const float x = grid[3 * p + 0];
    const float y = grid[3 * p + 1];
    const float r = grid[3 * p + 2];

    __shared__ float w[2 * H + 1];
    __shared__ float s_wsum;
    __shared__ float t[MAX_OH][MAX_TW];

    const float sigma = r / 3.0f;
    const float half  = ceilf(2.0f * sigma);
    if (tid < 2 * H + 1) {
        float pos = (float)(tid - H);
        float v   = expf(-0.5f * (pos / sigma) * (pos / sigma));
        w[tid]    = (fabsf(pos) <= half) ? v : 0.0f;
    }
    __syncthreads();
    if (tid == 0) {
        float s = 0.0f;
        #pragma unroll
        for (int k = 0; k < 2 * H + 1; k++) s += w[k];
        s_wsum = s;
    }
    __syncthreads();

    // 0-based center
    const float cx = x - 1.0f, cy = y - 1.0f;
    const float r2 = r * r;

    int oy0 = max(0,        (int)floorf(cy - r) - H);
    int oy1 = min(SIZE - 1, (int)ceilf (cy + r) + H);
    int ox0 = max(0,        (int)floorf(cx - r) - H);
    int ox1 = min(SIZE - 1, (int)ceilf (cx + r) + H);

    // intermediate column range (covers all reflected horizontal taps)
    int cLo = max(0,        ox0 - H);
    int cHi = min(SIZE - 1, ox1 + H);

    int oh = oy1 - oy0 + 1;           // <= 52
    int ow = ox1 - ox0 + 1;           // <= 52
    int tw = cHi - cLo + 1;           // <= 72
    if (oh > MAX_OH) oh = MAX_OH;     // safety clamps (never expected to fire)
    if (tw > MAX_TW) tw = MAX_TW;

    // --- vertical pass: t[i][c] = sum_dy w[dy] * mask(refl(row+dy), col) ---
    for (int idx = tid; idx < oh * tw; idx += blockDim.x) {
        int i   = idx / tw;
        int c   = idx - i * tw;
        int row = oy0 + i;
        int col = cLo + c;
        float dxc = (float)(col + 1) - x;   // coordinate is index+1
        float dx2 = dxc * dxc;
        float acc = 0.0f;
        #pragma unroll
        for (int dy = -H; dy <= H; dy++) {
            int   m   = refl(row + dy);
            float dyc = (float)(m + 1) - y;
            float inside = (dx2 + dyc * dyc <= r2) ? 1.0f : 0.0f;
            acc = fmaf(w[dy + H], inside, acc);
        }
        t[i][c] = acc;
    }
    __syncthreads();

    // --- horizontal pass + threshold + scatter ---
    const float wsum  = s_wsum;
    const float scale = bright / (wsum * wsum);
    for (int idx = tid; idx < oh * ow; idx += blockDim.x) {
        int i   = idx / ow;
        int j   = idx - i * ow;
        int col = ox0 + j;
        float acc = 0.0f;
        #pragma unroll
        for (int dx = -H; dx <= H; dx++) {
            int cc = refl(col + dx) - cLo;
            acc = fmaf(w[dx + H], t[i][cc], acc);
        }
        float val = acc * scale;
        if (val >= THRESH) {
            atomicAdd(&img[(oy0 + i) * SIZE + (ox0 + j)], val);
        }
    }
}

// ---------------------------------------------------------------------------
// K2: clamp to 1.0 in place, reduce global max
// ---------------------------------------------------------------------------
__global__ void k_clamp_max(float* __restrict__ img) {
    int i = blockIdx.x * blockDim.x + threadIdx.x;
    float v = 0.0f;
    if (i < SIZE * SIZE) {
        v = fminf(img[i], 1.0f);
        img[i] = v;
    }
    // warp reduce max
    #pragma unroll
    for (int off = 16; off > 0; off >>= 1)
        v = fmaxf(v, __shfl_xor_sync(0xffffffffu, v, off));
    __shared__ float smax[8];
    int lane = threadIdx.x & 31, wid = threadIdx.x >> 5;
    if (lane == 0) smax[wid] = v;
    __syncthreads();
    if (wid == 0) {
        v = (lane < (blockDim.x >> 5)) ? smax[lane] : 0.0f;
        #pragma unroll
        for (int off = 4; off > 0; off >>= 1)
            v = fmaxf(v, __shfl_xor_sync(0xffffffffu, v, off));
        if (lane == 0) atomicMax(&g_max_bits, __float_as_int(v));
    }
}

// ---------------------------------------------------------------------------
// K3: divide by max (if > 0)
// ---------------------------------------------------------------------------
__global__ void k_norm(float* __restrict__ img) {
    int i = blockIdx.x * blockDim.x + threadIdx.x;
    float m = __int_as_float(g_max_bits);
    if (i < SIZE * SIZE && m > 0.0f) img[i] = img[i] / m;
}

extern "C" void kernel_launch(void* const* d_in, const int* in_sizes, int n_in,
                              void* d_out, int out_size) {
    const float* phos = (const float*)d_in[0];
    const float* grid = (const float*)d_in[1];
    // defensive: metadata order is phoscoding(256), grid(768)
    if (n_in >= 2 && in_sizes[0] == 3 * N_PHOS && in_sizes[1] == N_PHOS) {
        const float* tmp = phos; phos = grid; grid = tmp;
    }
    float* img = (float*)d_out;

    const int threads = 256;
    const int pix_blocks = (SIZE * SIZE + threads - 1) / threads;

    k_zero<<<pix_blocks, threads>>>(img);
    k_phos<<<N_PHOS, threads>>>(phos, grid, img);
    k_clamp_max<<<pix_blocks, threads>>>(img);
    k_norm<<<pix_blocks, threads>>>(img);
}